// round 15
// baseline (speedup 1.0000x reference)
#include <cuda_runtime.h>
#include <math.h>

// ---------------------------------------------------------------------------
// Kalman filter + RTS smoother, T=4096, DZ=DX=64.
// Covariance chains are data-independent and contracting: compute only the
// first NC forward steps and (NTAIL tail + NC head) backward steps exactly.
// Smoother gains C are computed OFF the sequential chain in a parallel kernel.
// Backward tail and head run as TWO CONCURRENT CTAs; the head's start value
// (steady smoothed covariance) comes from fixed-point doubling (log steps).
// Means-forward overlaps the covariance chain, paced by an atomic flag.
// logdet terms summed post-loop via __ldcg (stale-L1 line-sharing hazard).
// ---------------------------------------------------------------------------

static constexpr int TT    = 4096;
static constexpr int NC    = 96;              // forward covariance steps computed exactly
static constexpr int NTAIL = 96;              // backward smoother tail steps computed exactly
static constexpr int TB    = TT - 1 - NTAIL;  // tail region is [TB, T-2]
static constexpr int NN    = 64 * 64;
static constexpr int ROW   = 68;              // padded smem row stride
static constexpr int MAT   = 64 * ROW;
static constexpr int NT    = 512;             // threads for covariance kernels

// ----- device scratch (static device globals: allowed; no allocation) -----
__device__ float g_pP  [(size_t)NC * NN];
__device__ float g_AP  [(size_t)NC * NN];
__device__ float g_fP  [(size_t)NC * NN];
__device__ float g_K   [(size_t)NC * NN];
__device__ float g_Sinv[(size_t)NC * NN];
__device__ float g_C   [(size_t)NC * NN];
__device__ float g_CT  [(size_t)NC * NN];
__device__ float g_logdet[NC];
__device__ float g_HA[NN];
__device__ float g_bh[64];
__device__ float g_pm[(size_t)TT * 64];
__device__ float g_fm[(size_t)TT * 64];
__device__ float g_sPbss[NN];
__device__ int   g_ready;   // forward-chain progress flag (monotone per run)

// ----- packed f32x2 helpers (sm_103a) --------------------------------------
#define FMA2(d, a, b, c) \
    asm("fma.rn.f32x2 %0, %1, %2, %3;" : "=l"(d) : "l"(a), "l"(b), "l"(c))
#define PACK2(d, lo, hi) \
    asm("mov.b64 %0, {%1, %2};" : "=l"(d) : "r"(lo), "r"(hi))
#define UNPACK2(lo, hi, v) \
    asm("mov.b64 {%0, %1}, %2;" : "=r"(lo), "=r"(hi) : "l"(v))

// ---------------------------------------------------------------------------
// 64x64 GEMM, 512 threads, 2x4 register tiles, f32x2 packed FMAs.
//   op(A)[r][k] = TAS ? A[r*ROW+k] : A[k*ROW+r]   (TAS=false => op(A)=A_st^T)
//   B[k][c] = B[k*ROW+c]
// MODE: 0 C=op(A)B ; 1 C=op(A)B+D ; 2 C=D-op(A)B.  C stride CS, D stride DS.
// Optional G: mirror result to gmem row-major (stride 64).  Optional CT:
// also write the transpose (stride 64).
// ---------------------------------------------------------------------------
template<int MODE, bool TAS, int CS, int DS>
__device__ __forceinline__ void gemm64(float* C, const float* A, const float* B,
                                       const float* D, float* G = nullptr,
                                       float* CT = nullptr)
{
    __syncthreads();
    const int tid = threadIdx.x;
    const int r0 = (tid >> 4) << 1;   // 0..62 (step 2)
    const int c0 = (tid & 15) << 2;   // 0..60
    unsigned long long acc[2][2];
    acc[0][0] = acc[0][1] = acc[1][0] = acc[1][1] = 0ull;

    #pragma unroll 8
    for (int k = 0; k < 64; k++) {
        float a0, a1;
        if (TAS) {
            a0 = A[(r0 + 0) * ROW + k];
            a1 = A[(r0 + 1) * ROW + k];
        } else {
            const float2 v = *(const float2*)(A + k * ROW + r0);
            a0 = v.x; a1 = v.y;
        }
        const unsigned long long b01 = *(const unsigned long long*)(B + k * ROW + c0);
        const unsigned long long b23 = *(const unsigned long long*)(B + k * ROW + c0 + 2);
        unsigned long long aa;
        unsigned int u;
        u = __float_as_uint(a0); PACK2(aa, u, u);
        FMA2(acc[0][0], aa, b01, acc[0][0]); FMA2(acc[0][1], aa, b23, acc[0][1]);
        u = __float_as_uint(a1); PACK2(aa, u, u);
        FMA2(acc[1][0], aa, b01, acc[1][0]); FMA2(acc[1][1], aa, b23, acc[1][1]);
    }

    #pragma unroll
    for (int i = 0; i < 2; i++) {
        #pragma unroll
        for (int p = 0; p < 2; p++) {
            unsigned int ulo, uhi;
            UNPACK2(ulo, uhi, acc[i][p]);
            float v0 = __uint_as_float(ulo);
            float v1 = __uint_as_float(uhi);
            const int r = r0 + i, ca = c0 + 2 * p, cb = ca + 1;
            if (MODE == 1) { v0 += D[r * DS + ca]; v1 += D[r * DS + cb]; }
            if (MODE == 2) { v0 = D[r * DS + ca] - v0; v1 = D[r * DS + cb] - v1; }
            C[r * CS + ca] = v0;
            C[r * CS + cb] = v1;
            if (G)  { G[r * 64 + ca] = v0; G[r * 64 + cb] = v1; }
            if (CT) { CT[ca * 64 + r] = v0; CT[cb * 64 + r] = v1; }
        }
    }
    __syncthreads();
}

// ----- stride-converting float4 copies (NT threads) -------------------------
__device__ __forceinline__ void g2s(float* dst, const float* src) // gmem(64)->smem(ROW)
{
    for (int idx = threadIdx.x; idx < 1024; idx += NT) {
        const int r = idx >> 4, c4 = idx & 15;
        ((float4*)dst)[r * (ROW / 4) + c4] = ((const float4*)src)[r * 16 + c4];
    }
    __syncthreads();
}
__device__ __forceinline__ void s2g(float* dst, const float* src) // smem(ROW)->gmem(64)
{
    for (int idx = threadIdx.x; idx < 1024; idx += NT) {
        const int r = idx >> 4, c4 = idx & 15;
        ((float4*)dst)[r * 16 + c4] = ((const float4*)src)[r * (ROW / 4) + c4];
    }
    __syncthreads();
}
__device__ __forceinline__ void s2s(float* dst, const float* src)
{
    for (int idx = threadIdx.x; idx < MAT / 4; idx += NT)
        ((float4*)dst)[idx] = ((const float4*)src)[idx];
    __syncthreads();
}

// ---------------------------------------------------------------------------
// In-place LDL^T of SPD 64x64 (raw columns: S[i][k] = l'_{ik} * d_k).
// 512 threads: 8 threads per row, 8 cols each; one barrier per round.
// ---------------------------------------------------------------------------
__device__ void chol_ldl(float* S, float* dv, float* rdv)
{
    __shared__ float s_rd[64];
    const int tid = threadIdx.x;
    if (tid == 0) {
        const float d0 = S[0];
        dv[0] = d0;
        const float r = __frcp_rn(d0);
        rdv[0] = r; s_rd[0] = r;
    }
    __syncthreads();
    for (int k = 0; k < 63; k++) {
        const float rd = s_rd[k];
        const int i = k + 1 + (tid >> 3);
        if (i < 64) {
            const float f = S[i * ROW + k] * rd;
            const int j0 = (tid & 7) * 8;
            #pragma unroll
            for (int jj = 0; jj < 8; jj++) {
                const int j = j0 + jj;
                if (j > k && j <= i) {
                    const float nv = S[i * ROW + j] - f * S[j * ROW + k];
                    S[i * ROW + j] = nv;
                    if (i == k + 1 && j == k + 1) {     // exactly one thread
                        dv[k + 1] = nv;
                        const float r1 = __frcp_rn(nv);
                        rdv[k + 1] = r1; s_rd[k + 1] = r1;
                    }
                }
            }
        }
        __syncthreads();
    }
}

// X = Linv for L = L' diag(sqrt(d)):  X = diag(d^{-1/2}) L'^{-1}.  512 thr.
__device__ void triinv_scaled(float* X, const float* S, const float* rdv,
                              const float* dv)
{
    const int tid = threadIdx.x;
    for (int idx = tid; idx < MAT; idx += NT) X[idx] = 0.0f;
    __syncthreads();
    if (tid < 64) X[tid * ROW + tid] = 1.0f;
    __syncthreads();
    for (int i = 0; i < 64; i++) {
        const int m = i + 1 + (tid >> 3);
        if (m < 64) {
            const float lmi = S[m * ROW + i] * rdv[i];
            const int j0 = (tid & 7) * 8;
            #pragma unroll
            for (int jj = 0; jj < 8; jj++) {
                const int j = j0 + jj;
                if (j <= i) X[m * ROW + j] -= lmi * X[i * ROW + j];
            }
        }
        __syncthreads();
    }
    {
        const int r = tid >> 3;
        const float sc = rsqrtf(dv[r]);
        const int j0 = (tid & 7) * 8;
        #pragma unroll
        for (int jj = 0; jj < 8; jj++) X[r * ROW + j0 + jj] *= sc;
    }
    __syncthreads();
}

// ---------------------------------------------------------------------------
// Kernel 1: forward covariance chain (NC steps, single CTA, 512 threads).
// Gains deferred.  Publishes per-step completion in g_ready.
// ---------------------------------------------------------------------------
__global__ void __launch_bounds__(NT)
k_cov_forward(const float* __restrict__ Ag, const float* __restrict__ bg,
              const float* __restrict__ Qg, const float* __restrict__ Hg,
              const float* __restrict__ cg, const float* __restrict__ Rg,
              const float* __restrict__ prior_cov)
{
    extern __shared__ float sm[];
    float* AsT = sm + 0 * MAT;
    float* As  = sm + 1 * MAT;
    float* HsT = sm + 2 * MAT;
    float* Qs  = sm + 3 * MAT;
    float* Rs  = sm + 4 * MAT;
    float* M0  = sm + 5 * MAT;   // fP (carried)
    float* M1  = sm + 6 * MAT;   // AP / HP
    float* M2  = sm + 7 * MAT;   // pP
    float* M3  = sm + 8 * MAT;   // LDL factor
    float* M4  = sm + 9 * MAT;   // Linv / K
    float* M5  = sm + 10 * MAT;  // Sinv
    __shared__ float dv[64], rdv[64];

    const int tid = threadIdx.x;
    for (int idx = tid; idx < NN; idx += NT) {
        const int r = idx >> 6, cc = idx & 63;
        const float va = Ag[idx];
        AsT[cc * ROW + r] = va;
        As[r * ROW + cc]  = va;
        HsT[cc * ROW + r] = Hg[idx];
    }
    __syncthreads();
    g2s(Qs, Qg);
    g2s(Rs, Rg);

    // one-time precompute for the means kernel: HA = H @ A, bh = H b + c
    gemm64<0, false, 64, ROW>(g_HA, HsT, As, nullptr);
    if (tid < 64) {
        float s = cg[tid];
        #pragma unroll 8
        for (int k = 0; k < 64; k++) s += Hg[tid * 64 + k] * bg[k];
        g_bh[tid] = s;
    }
    __syncthreads();

    for (int t = 0; t < NC; t++) {
        if (t == 0) {
            g2s(M2, prior_cov);                                         // pP_0
        } else {
            gemm64<0, false, ROW, ROW>(M1, AsT, M0, nullptr,
                                       g_AP + (size_t)t * NN);          // AP = A fP
            gemm64<1, true,  ROW, ROW>(M2, M1, AsT, Qs,
                                       g_pP + (size_t)t * NN);          // pP = AP A^T + Q
        }
        gemm64<0, false, ROW, ROW>(M1, HsT, M2, nullptr);               // HP = H pP
        gemm64<1, true,  ROW, ROW>(M3, M1, HsT, Rs);                    // S = HP H^T + R
        chol_ldl(M3, dv, rdv);
        if (tid < 32) {                                                 // logdet
            float v = __logf(dv[tid]) + __logf(dv[tid + 32]);
            #pragma unroll
            for (int o = 16; o > 0; o >>= 1) v += __shfl_down_sync(0xffffffffu, v, o);
            if (tid == 0) g_logdet[t] = 0.5f * v;
        }
        triinv_scaled(M4, M3, rdv, dv);                                 // Linv
        gemm64<0, false, ROW, ROW>(M5, M4, M4, nullptr,
                                   g_Sinv + (size_t)t * NN);            // Sinv
        gemm64<0, false, ROW, ROW>(M4, M1, M5, nullptr,
                                   g_K + (size_t)t * NN);               // K = HP^T Sinv
        gemm64<2, true,  ROW, ROW>(M0, M4, M1, M2,
                                   g_fP + (size_t)t * NN);              // fP = pP - K HP
        __threadfence();
        __syncthreads();
        if (tid == 0) atomicExch(&g_ready, t + 1);
    }
}

// ---------------------------------------------------------------------------
// Kernel 1b: smoother gains, fully parallel across time (NC-1 CTAs).
// CTA j handles t=j+1: C_j = AP_t^T pP_t^{-1}.
// ---------------------------------------------------------------------------
__global__ void __launch_bounds__(NT)
k_gains()
{
    extern __shared__ float sm[];
    float* APs = sm + 0 * MAT;
    float* M3  = sm + 1 * MAT;
    float* X   = sm + 2 * MAT;
    float* Pi  = sm + 3 * MAT;
    __shared__ float dv[64], rdv[64];
    const int t = blockIdx.x + 1;

    g2s(APs, g_AP + (size_t)t * NN);
    g2s(M3,  g_pP + (size_t)t * NN);
    chol_ldl(M3, dv, rdv);
    triinv_scaled(X, M3, rdv, dv);
    gemm64<0, false, ROW, ROW>(Pi, X, X, nullptr);                      // pPinv
    gemm64<0, false, 64,  ROW>(g_C + (size_t)(t - 1) * NN, APs, Pi,
                               nullptr, nullptr,
                               g_CT + (size_t)(t - 1) * NN);            // C = AP^T pPinv
}

// ---------------------------------------------------------------------------
// Kernel 2: forward means + log-likelihood (256 threads); runs CONCURRENTLY
// with kernel 1, self-paced via g_ready.  logdet summed post-loop (__ldcg).
// ---------------------------------------------------------------------------
__global__ void __launch_bounds__(256)
k_means_forward(const float* __restrict__ obs, const float* __restrict__ Ag,
                const float* __restrict__ bg, const float* __restrict__ Hg,
                const float* __restrict__ cg, const float* __restrict__ pm0,
                float* __restrict__ out_ll)
{
    __shared__ float x[64], o1[128], o2[128], rres[64];
    const int tid = threadIdx.x;
    const int row = tid >> 1, h = tid & 1;
    double ll = 0.0;
    const float llc = -58.81206612509907f;   // -0.5 * 64 * log(2*pi)

    for (int t = 0; t < TT; t++) {
        const int tc = (t < NC) ? t : (NC - 1);
        if (t < NC) {                         // pace behind the producer
            if (tid == 0)
                while (atomicAdd(&g_ready, 0) < t + 1) __nanosleep(200);
            __syncthreads();
        }
        if (t == 0) {
            if (tid < 64) x[tid] = pm0[tid];
            __syncthreads();
            if (row < 64) {
                if (h == 0) o1[row] = x[row];                  // pm = prior_mean
            } else {
                const float4* M4 = (const float4*)(Hg + (row - 64) * 64 + h * 32);
                float s = 0.0f;
                #pragma unroll
                for (int q = 0; q < 8; q++) {
                    const float4 v = M4[q];
                    const int k = h * 32 + q * 4;
                    s += v.x * x[k] + v.y * x[k + 1] + v.z * x[k + 2] + v.w * x[k + 3];
                }
                s += __shfl_down_sync(0xffffffffu, s, 1, 2);
                if (h == 0) o1[row] = s + cg[row - 64];        // yhat
            }
            __syncthreads();
        } else {
            const float* Mr = (row < 64) ? (Ag + row * 64) : (g_HA + (row - 64) * 64);
            const float add = (row < 64) ? bg[row] : g_bh[row - 64];
            const float4* M4 = (const float4*)(Mr + h * 32);
            float s = 0.0f;
            #pragma unroll
            for (int q = 0; q < 8; q++) {
                const float4 v = M4[q];
                const int k = h * 32 + q * 4;
                s += v.x * x[k] + v.y * x[k + 1] + v.z * x[k + 2] + v.w * x[k + 3];
            }
            s += __shfl_down_sync(0xffffffffu, s, 1, 2);
            if (h == 0) o1[row] = s + add;
            __syncthreads();
        }

        if (tid < 64) {
            g_pm[(size_t)t * 64 + tid] = o1[tid];
            rres[tid] = obs[(size_t)t * 64 + tid] - o1[64 + tid];   // r = y - yhat
        }
        __syncthreads();

        // o2[0:64)= Sinv r ; o2[64:128)= K r
        {
            const float* Mr = (row < 64)
                ? (g_Sinv + (size_t)tc * NN + row * 64)
                : (g_K + (size_t)tc * NN + (row - 64) * 64);
            const float4* M4 = (const float4*)(Mr + h * 32);
            float s = 0.0f;
            #pragma unroll
            for (int q = 0; q < 8; q++) {
                const float4 v = M4[q];
                const int k = h * 32 + q * 4;
                s += v.x * rres[k] + v.y * rres[k + 1] + v.z * rres[k + 2] + v.w * rres[k + 3];
            }
            s += __shfl_down_sync(0xffffffffu, s, 1, 2);
            if (h == 0) o2[row] = s;
        }
        __syncthreads();

        if (tid < 32) {
            float p = rres[tid] * o2[tid] + rres[tid + 32] * o2[tid + 32];
            #pragma unroll
            for (int o = 16; o > 0; o >>= 1) p += __shfl_down_sync(0xffffffffu, p, o);
            if (tid == 0) ll += (double)(llc - 0.5f * p);
        }
        if (tid < 64) {
            const float f = o1[tid] + o2[64 + tid];            // fm = pm + K r
            x[tid] = f;
            g_fm[(size_t)t * 64 + tid] = f;
        }
        __syncthreads();
    }

    // logdet contribution: producer fully done (loop paced to t=NC-1).
    if (tid == 0) {
        double lds = 0.0;
        for (int t = 0; t < NC - 1; t++) lds += (double)__ldcg(&g_logdet[t]);
        lds += (double)(TT - (NC - 1)) * (double)__ldcg(&g_logdet[NC - 1]);
        *out_ll = (float)(ll - lds);
    }
}

// ---------------------------------------------------------------------------
// Kernel 3: backward smoothed covariances.  grid=2:
//   CTA 0: tail region [TB, T-2] (steady coefficients), sequential NTAIL.
//   CTA 1: fixed-point doubling to get steady sP (log steps), writes g_sPbss,
//          then head region [0, NC-1] with exact per-t coefficients.
// Disjoint outputs — fully concurrent.
// ---------------------------------------------------------------------------
__global__ void __launch_bounds__(NT)
k_cov_backward(float* __restrict__ out_cov)
{
    extern __shared__ float sm[];
    float* sP  = sm + 0 * MAT;   // carried sP  (CTA1: doubling B)
    float* Cst = sm + 1 * MAT;   // C^T         (CTA1: doubling M^T)
    float* Dm  = sm + 2 * MAT;   // temp
    float* Em  = sm + 3 * MAT;   // temp
    float* pPs = sm + 4 * MAT;   // steady pP
    float* Tm  = sm + 5 * MAT;   // doubling temp
    const int tid = threadIdx.x;

    const float* fPs = g_fP + (size_t)(NC - 1) * NN;

    if (blockIdx.x == 0) {
        // ---- tail: t = T-1 then [TB, T-2], steady coefficients ----
        g2s(sP, fPs);
        s2g(out_cov + (size_t)(TT - 1) * NN, sP);
        g2s(Cst, g_CT + (size_t)(NC - 2) * NN);
        g2s(pPs, g_pP + (size_t)(NC - 1) * NN);
        for (int t = TT - 2; t >= TB; t--) {
            for (int idx = tid; idx < MAT / 4; idx += NT)
                ((float4*)Dm)[idx] = make_float4(
                    ((const float4*)sP)[idx].x - ((const float4*)pPs)[idx].x,
                    ((const float4*)sP)[idx].y - ((const float4*)pPs)[idx].y,
                    ((const float4*)sP)[idx].z - ((const float4*)pPs)[idx].z,
                    ((const float4*)sP)[idx].w - ((const float4*)pPs)[idx].w);
            gemm64<0, false, ROW, ROW>(Em, Cst, Dm, nullptr);  // E = C (sP - pP)
            gemm64<1, true,  ROW, 64 >(sP, Em, Cst, fPs);      // sP = fP + E C^T
            s2g(out_cov + (size_t)t * NN, sP);
        }
    } else {
        // ---- doubling: fixed point of  sP -> C sP C^T + G,
        //      G = fP_ss - C pP_ss C^T.  M_t stored transposed in Cst. ----
        g2s(Cst, g_CT + (size_t)(NC - 2) * NN);                 // M^T = C^T
        g2s(pPs, g_pP + (size_t)(NC - 1) * NN);
        gemm64<0, false, ROW, ROW>(Tm, Cst, pPs, nullptr);      // T = C pP
        gemm64<2, true,  ROW, 64 >(sP, Tm, Cst, fPs);           // B = fP - T C^T
        float* Mt = Cst;
        float* Sq = Em;
        for (int it = 0; it < 8; it++) {
            gemm64<0, false, ROW, ROW>(Tm, Mt, sP, nullptr);    // T = M B
            gemm64<1, true,  ROW, ROW>(sP, Tm, Mt, sP);         // B += T M^T
            gemm64<0, true,  ROW, ROW>(Sq, Mt, Mt, nullptr);    // (M^2)^T = M^T M^T
            float* tmp = Mt; Mt = Sq; Sq = tmp;                 // M <- M^2
        }
        s2g(g_sPbss, sP);                                       // steady value

        // ---- head region [0, NC-1], exact per-t coefficients ----
        for (int t = NC - 1; t >= 0; t--) {
            const int tcC = (t < NC - 1) ? t : (NC - 2);
            const int tcn = (t + 1 < NC) ? (t + 1) : (NC - 1);
            g2s(Sq, g_CT + (size_t)tcC * NN);                   // C^T for this t
            const float4* gpP = (const float4*)(g_pP + (size_t)tcn * NN);
            for (int idx = tid; idx < 1024; idx += NT) {
                const int r = idx >> 4, c4 = idx & 15;
                const float4 a = ((const float4*)sP)[r * (ROW / 4) + c4];
                const float4 p = gpP[r * 16 + c4];
                ((float4*)Dm)[r * (ROW / 4) + c4] =
                    make_float4(a.x - p.x, a.y - p.y, a.z - p.z, a.w - p.w);
            }
            gemm64<0, false, ROW, ROW>(Tm, Sq, Dm, nullptr);    // T = C (sP - pP)
            gemm64<1, true,  ROW, 64 >(sP, Tm, Sq, g_fP + (size_t)t * NN);
            s2g(out_cov + (size_t)t * NN, sP);
        }
    }
}

// Kernel 4: fill the converged middle region [NC, TB) with the steady value.
__global__ void k_fill(float* __restrict__ out_cov)
{
    const size_t start = (size_t)NC * NN;
    const size_t end   = (size_t)TB * NN;
    const size_t stride = (size_t)gridDim.x * blockDim.x;
    for (size_t i = start + (size_t)blockIdx.x * blockDim.x + threadIdx.x;
         i < end; i += stride)
        out_cov[i] = g_sPbss[i & (NN - 1)];
}

// ---------------------------------------------------------------------------
// Kernel 5: backward smoothed means (all T steps, 256 threads).
// ---------------------------------------------------------------------------
__global__ void __launch_bounds__(256)
k_means_backward(float* __restrict__ out_sm)
{
    __shared__ float smv[64], d[64];
    const int tid = threadIdx.x;
    const int row = tid >> 2, q = tid & 3;
    if (tid < 64) {
        const float v = g_fm[(size_t)(TT - 1) * 64 + tid];
        smv[tid] = v;
        out_sm[(size_t)(TT - 1) * 64 + tid] = v;
    }
    __syncthreads();
    for (int t = TT - 2; t >= 0; t--) {
        const int tcC = (t < NC - 1) ? t : (NC - 2);
        if (tid < 64) d[tid] = smv[tid] - g_pm[(size_t)(t + 1) * 64 + tid];
        __syncthreads();
        const float4* M4 = (const float4*)(g_C + (size_t)tcC * NN + row * 64 + q * 16);
        float s = 0.0f;
        #pragma unroll
        for (int p = 0; p < 4; p++) {
            const float4 v = M4[p];
            const int k = q * 16 + p * 4;
            s += v.x * d[k] + v.y * d[k + 1] + v.z * d[k + 2] + v.w * d[k + 3];
        }
        s += __shfl_down_sync(0xffffffffu, s, 2, 4);
        s += __shfl_down_sync(0xffffffffu, s, 1, 4);
        if (q == 0) {
            const float nv = g_fm[(size_t)t * 64 + row] + s;
            smv[row] = nv;
            out_sm[(size_t)t * 64 + row] = nv;
        }
        __syncthreads();
    }
}

// ---------------------------------------------------------------------------
extern "C" void kernel_launch(void* const* d_in, const int* in_sizes, int n_in,
                              void* d_out, int out_size)
{
    (void)in_sizes; (void)n_in; (void)out_size;
    const float* obs = (const float*)d_in[0];
    const float* A   = (const float*)d_in[1];
    const float* b   = (const float*)d_in[2];
    const float* Q   = (const float*)d_in[3];
    const float* H   = (const float*)d_in[4];
    const float* c   = (const float*)d_in[5];
    const float* R   = (const float*)d_in[6];
    const float* pm0 = (const float*)d_in[7];
    const float* pP0 = (const float*)d_in[8];

    float* out     = (float*)d_out;
    float* out_sm  = out;                                        // [T,64]
    float* out_cov = out + (size_t)TT * 64;                      // [T,64,64]
    float* out_ll  = out + (size_t)TT * 64 + (size_t)TT * NN;    // scalar

    static cudaStream_t s2 = nullptr;
    static cudaEvent_t ev0, evG, evE;
    if (!s2) {
        cudaStreamCreateWithFlags(&s2, cudaStreamNonBlocking);
        cudaEventCreateWithFlags(&ev0, cudaEventDisableTiming);
        cudaEventCreateWithFlags(&evG, cudaEventDisableTiming);
        cudaEventCreateWithFlags(&evE, cudaEventDisableTiming);
        cudaFuncSetAttribute((const void*)k_cov_forward,
                             cudaFuncAttributeMaxDynamicSharedMemorySize,
                             11 * MAT * (int)sizeof(float));
        cudaFuncSetAttribute((const void*)k_gains,
                             cudaFuncAttributeMaxDynamicSharedMemorySize,
                             4 * MAT * (int)sizeof(float));
        cudaFuncSetAttribute((const void*)k_cov_backward,
                             cudaFuncAttributeMaxDynamicSharedMemorySize,
                             6 * MAT * (int)sizeof(float));
    }

    // Fork: means_forward runs concurrently with cov_forward (flag-paced).
    cudaEventRecord(ev0, 0);
    cudaStreamWaitEvent(s2, ev0, 0);
    k_means_forward<<<1, 256, 0, s2>>>(obs, A, b, H, c, pm0, out_ll);

    k_cov_forward<<<1, NT, 11 * MAT * sizeof(float)>>>(A, b, Q, H, c, R, pP0);
    k_gains<<<NC - 1, NT, 4 * MAT * sizeof(float)>>>();
    cudaEventRecord(evG, 0);
    k_cov_backward<<<2, NT, 6 * MAT * sizeof(float)>>>(out_cov);
    k_fill<<<1024, 256>>>(out_cov);

    cudaStreamWaitEvent(s2, evG, 0);          // means_backward needs g_C
    k_means_backward<<<1, 256, 0, s2>>>(out_sm);

    cudaEventRecord(evE, s2);                 // join
    cudaStreamWaitEvent(0, evE, 0);
}

// round 16
// speedup vs baseline: 2.1255x; 2.1255x over previous
#include <cuda_runtime.h>
#include <math.h>

// ---------------------------------------------------------------------------
// Kalman filter + RTS smoother, T=4096, DZ=DX=64.
// Covariance chains are data-independent and contracting: compute only the
// first NC forward steps and (NTAIL tail + NC head) backward steps exactly.
// Smoother gains C computed OFF the sequential chain in a parallel kernel.
// Backward tail and head run as TWO CONCURRENT CTAs (head seeded by
// fixed-point doubling).  Means-forward overlaps the covariance chain
// (atomic-flag paced); means kernels keep their hot matrices in SMEM.
// ---------------------------------------------------------------------------

static constexpr int TT    = 4096;
static constexpr int NC    = 96;              // forward covariance steps computed exactly
static constexpr int NTAIL = 96;              // backward smoother tail steps computed exactly
static constexpr int TB    = TT - 1 - NTAIL;  // tail region is [TB, T-2]
static constexpr int NN    = 64 * 64;
static constexpr int ROW   = 68;              // padded smem row stride
static constexpr int MAT   = 64 * ROW;
static constexpr int NT    = 256;             // threads for covariance kernels

// ----- device scratch (static device globals: allowed; no allocation) -----
__device__ float g_pP  [(size_t)NC * NN];
__device__ float g_AP  [(size_t)NC * NN];
__device__ float g_fP  [(size_t)NC * NN];
__device__ float g_K   [(size_t)NC * NN];
__device__ float g_Sinv[(size_t)NC * NN];
__device__ float g_C   [(size_t)NC * NN];
__device__ float g_CT  [(size_t)NC * NN];
__device__ float g_logdet[NC];
__device__ float g_HA[NN];
__device__ float g_bh[64];
__device__ float g_pm[(size_t)TT * 64];
__device__ float g_fm[(size_t)TT * 64];
__device__ float g_sPbss[NN];
__device__ int   g_ready;   // forward-chain progress flag (monotone per run)

// ----- packed f32x2 helpers (sm_103a) --------------------------------------
#define FMA2(d, a, b, c) \
    asm("fma.rn.f32x2 %0, %1, %2, %3;" : "=l"(d) : "l"(a), "l"(b), "l"(c))
#define PACK2(d, lo, hi) \
    asm("mov.b64 %0, {%1, %2};" : "=l"(d) : "r"(lo), "r"(hi))
#define UNPACK2(lo, hi, v) \
    asm("mov.b64 {%0, %1}, %2;" : "=r"(lo), "=r"(hi) : "l"(v))

// ---------------------------------------------------------------------------
// 64x64 GEMM, 256 threads, 4x4 register tiles, f32x2 packed FMAs.
//   op(A)[r][k] = TAS ? A[r*ROW+k] : A[k*ROW+r]   (TAS=false => op(A)=A_st^T)
//   B[k][c] = B[k*ROW+c]
// MODE: 0 C=op(A)B ; 1 C=op(A)B+D ; 2 C=D-op(A)B.  C stride CS, D stride DS.
// Optional G: mirror result to gmem row-major (stride 64).  Optional CT:
// also write the transpose (stride 64).
// ---------------------------------------------------------------------------
template<int MODE, bool TAS, int CS, int DS>
__device__ __forceinline__ void gemm64(float* C, const float* A, const float* B,
                                       const float* D, float* G = nullptr,
                                       float* CT = nullptr)
{
    __syncthreads();
    const int tid = threadIdx.x;
    const int r0 = (tid >> 4) << 2;
    const int c0 = (tid & 15) << 2;
    unsigned long long acc[4][2];
    #pragma unroll
    for (int i = 0; i < 4; i++) { acc[i][0] = 0ull; acc[i][1] = 0ull; }

    #pragma unroll 8
    for (int k = 0; k < 64; k++) {
        float a0, a1, a2, a3;
        if (TAS) {
            a0 = A[(r0 + 0) * ROW + k];
            a1 = A[(r0 + 1) * ROW + k];
            a2 = A[(r0 + 2) * ROW + k];
            a3 = A[(r0 + 3) * ROW + k];
        } else {
            const float4 v = *(const float4*)(A + k * ROW + r0);
            a0 = v.x; a1 = v.y; a2 = v.z; a3 = v.w;
        }
        const unsigned long long b01 = *(const unsigned long long*)(B + k * ROW + c0);
        const unsigned long long b23 = *(const unsigned long long*)(B + k * ROW + c0 + 2);
        unsigned long long aa;
        unsigned int u;
        u = __float_as_uint(a0); PACK2(aa, u, u);
        FMA2(acc[0][0], aa, b01, acc[0][0]); FMA2(acc[0][1], aa, b23, acc[0][1]);
        u = __float_as_uint(a1); PACK2(aa, u, u);
        FMA2(acc[1][0], aa, b01, acc[1][0]); FMA2(acc[1][1], aa, b23, acc[1][1]);
        u = __float_as_uint(a2); PACK2(aa, u, u);
        FMA2(acc[2][0], aa, b01, acc[2][0]); FMA2(acc[2][1], aa, b23, acc[2][1]);
        u = __float_as_uint(a3); PACK2(aa, u, u);
        FMA2(acc[3][0], aa, b01, acc[3][0]); FMA2(acc[3][1], aa, b23, acc[3][1]);
    }

    #pragma unroll
    for (int i = 0; i < 4; i++) {
        #pragma unroll
        for (int p = 0; p < 2; p++) {
            unsigned int ulo, uhi;
            UNPACK2(ulo, uhi, acc[i][p]);
            float v0 = __uint_as_float(ulo);
            float v1 = __uint_as_float(uhi);
            const int r = r0 + i, ca = c0 + 2 * p, cb = ca + 1;
            if (MODE == 1) { v0 += D[r * DS + ca]; v1 += D[r * DS + cb]; }
            if (MODE == 2) { v0 = D[r * DS + ca] - v0; v1 = D[r * DS + cb] - v1; }
            C[r * CS + ca] = v0;
            C[r * CS + cb] = v1;
            if (G)  { G[r * 64 + ca] = v0; G[r * 64 + cb] = v1; }
            if (CT) { CT[ca * 64 + r] = v0; CT[cb * 64 + r] = v1; }
        }
    }
    __syncthreads();
}

// ----- stride-converting float4 copies (NT threads) -------------------------
__device__ __forceinline__ void g2s(float* dst, const float* src) // gmem(64)->smem(ROW)
{
    for (int idx = threadIdx.x; idx < 1024; idx += NT) {
        const int r = idx >> 4, c4 = idx & 15;
        ((float4*)dst)[r * (ROW / 4) + c4] = ((const float4*)src)[r * 16 + c4];
    }
    __syncthreads();
}
__device__ __forceinline__ void s2g(float* dst, const float* src) // smem(ROW)->gmem(64)
{
    for (int idx = threadIdx.x; idx < 1024; idx += NT) {
        const int r = idx >> 4, c4 = idx & 15;
        ((float4*)dst)[r * 16 + c4] = ((const float4*)src)[r * (ROW / 4) + c4];
    }
    __syncthreads();
}

// ---------------------------------------------------------------------------
// In-place LDL^T of SPD 64x64 (raw columns: S[i][k] = l'_{ik} * d_k).
// ONE barrier per round: the thread that computes the round-k update of
// S[k+1][k+1] also publishes d_{k+1} and 1/d_{k+1} for the next round.
// ---------------------------------------------------------------------------
__device__ void chol_ldl(float* S, float* dv, float* rdv)
{
    __shared__ float s_rd[64];
    const int tid = threadIdx.x;
    if (tid == 0) {
        const float d0 = S[0];
        dv[0] = d0;
        const float r = __frcp_rn(d0);
        rdv[0] = r; s_rd[0] = r;
    }
    __syncthreads();
    for (int k = 0; k < 63; k++) {
        const float rd = s_rd[k];
        const int i = k + 1 + (tid >> 2);
        if (i < 64) {
            const float f = S[i * ROW + k] * rd;
            const int j0 = (tid & 3) * 16;
            #pragma unroll
            for (int jj = 0; jj < 16; jj++) {
                const int j = j0 + jj;
                if (j > k && j <= i) {
                    const float nv = S[i * ROW + j] - f * S[j * ROW + k];
                    S[i * ROW + j] = nv;
                    if (i == k + 1 && j == k + 1) {     // exactly one thread
                        dv[k + 1] = nv;
                        const float r1 = __frcp_rn(nv);
                        rdv[k + 1] = r1; s_rd[k + 1] = r1;
                    }
                }
            }
        }
        __syncthreads();
    }
}

// X = Linv for L = L' diag(sqrt(d)):  X = diag(d^{-1/2}) L'^{-1}.
__device__ void triinv_scaled(float* X, const float* S, const float* rdv,
                              const float* dv)
{
    const int tid = threadIdx.x;
    for (int idx = tid; idx < MAT; idx += NT) X[idx] = 0.0f;
    __syncthreads();
    if (tid < 64) X[tid * ROW + tid] = 1.0f;
    __syncthreads();
    for (int i = 0; i < 64; i++) {
        const int m = i + 1 + (tid >> 2);
        if (m < 64) {
            const float lmi = S[m * ROW + i] * rdv[i];
            const int j0 = (tid & 3) * 16;
            #pragma unroll
            for (int jj = 0; jj < 16; jj++) {
                const int j = j0 + jj;
                if (j <= i) X[m * ROW + j] -= lmi * X[i * ROW + j];
            }
        }
        __syncthreads();
    }
    {
        const int r = tid >> 2;
        const float sc = rsqrtf(dv[r]);
        const int j0 = (tid & 3) * 16;
        #pragma unroll
        for (int jj = 0; jj < 16; jj++) X[r * ROW + j0 + jj] *= sc;
    }
    __syncthreads();
}

// ---------------------------------------------------------------------------
// Kernel 1: forward covariance chain (NC steps, single CTA, 256 threads).
// Gains deferred.  Publishes per-step completion in g_ready.
// ---------------------------------------------------------------------------
__global__ void __launch_bounds__(NT)
k_cov_forward(const float* __restrict__ Ag, const float* __restrict__ bg,
              const float* __restrict__ Qg, const float* __restrict__ Hg,
              const float* __restrict__ cg, const float* __restrict__ Rg,
              const float* __restrict__ prior_cov)
{
    extern __shared__ float sm[];
    float* AsT = sm + 0 * MAT;
    float* As  = sm + 1 * MAT;
    float* HsT = sm + 2 * MAT;
    float* Qs  = sm + 3 * MAT;
    float* Rs  = sm + 4 * MAT;
    float* M0  = sm + 5 * MAT;   // fP (carried)
    float* M1  = sm + 6 * MAT;   // AP / HP
    float* M2  = sm + 7 * MAT;   // pP
    float* M3  = sm + 8 * MAT;   // LDL factor
    float* M4  = sm + 9 * MAT;   // Linv / K
    float* M5  = sm + 10 * MAT;  // Sinv
    __shared__ float dv[64], rdv[64];

    const int tid = threadIdx.x;
    for (int idx = tid; idx < NN; idx += NT) {
        const int r = idx >> 6, cc = idx & 63;
        const float va = Ag[idx];
        AsT[cc * ROW + r] = va;
        As[r * ROW + cc]  = va;
        HsT[cc * ROW + r] = Hg[idx];
    }
    __syncthreads();
    g2s(Qs, Qg);
    g2s(Rs, Rg);

    // one-time precompute for the means kernel: HA = H @ A, bh = H b + c
    gemm64<0, false, 64, ROW>(g_HA, HsT, As, nullptr);
    if (tid < 64) {
        float s = cg[tid];
        #pragma unroll 8
        for (int k = 0; k < 64; k++) s += Hg[tid * 64 + k] * bg[k];
        g_bh[tid] = s;
    }
    __syncthreads();

    for (int t = 0; t < NC; t++) {
        if (t == 0) {
            g2s(M2, prior_cov);                                         // pP_0
        } else {
            gemm64<0, false, ROW, ROW>(M1, AsT, M0, nullptr,
                                       g_AP + (size_t)t * NN);          // AP = A fP
            gemm64<1, true,  ROW, ROW>(M2, M1, AsT, Qs,
                                       g_pP + (size_t)t * NN);          // pP = AP A^T + Q
        }
        gemm64<0, false, ROW, ROW>(M1, HsT, M2, nullptr);               // HP = H pP
        gemm64<1, true,  ROW, ROW>(M3, M1, HsT, Rs);                    // S = HP H^T + R
        chol_ldl(M3, dv, rdv);
        if (tid < 32) {                                                 // logdet
            float v = __logf(dv[tid]) + __logf(dv[tid + 32]);
            #pragma unroll
            for (int o = 16; o > 0; o >>= 1) v += __shfl_down_sync(0xffffffffu, v, o);
            if (tid == 0) g_logdet[t] = 0.5f * v;
        }
        triinv_scaled(M4, M3, rdv, dv);                                 // Linv
        gemm64<0, false, ROW, ROW>(M5, M4, M4, nullptr,
                                   g_Sinv + (size_t)t * NN);            // Sinv
        gemm64<0, false, ROW, ROW>(M4, M1, M5, nullptr,
                                   g_K + (size_t)t * NN);               // K = HP^T Sinv
        gemm64<2, true,  ROW, ROW>(M0, M4, M1, M2,
                                   g_fP + (size_t)t * NN);              // fP = pP - K HP
        __threadfence();
        __syncthreads();
        if (tid == 0) atomicExch(&g_ready, t + 1);
    }
}

// ---------------------------------------------------------------------------
// Kernel 1b: smoother gains, fully parallel across time (NC-1 CTAs).
// CTA j handles t=j+1: C_j = AP_t^T pP_t^{-1}.
// ---------------------------------------------------------------------------
__global__ void __launch_bounds__(NT)
k_gains()
{
    extern __shared__ float sm[];
    float* APs = sm + 0 * MAT;
    float* M3  = sm + 1 * MAT;
    float* X   = sm + 2 * MAT;
    float* Pi  = sm + 3 * MAT;
    __shared__ float dv[64], rdv[64];
    const int t = blockIdx.x + 1;

    g2s(APs, g_AP + (size_t)t * NN);
    g2s(M3,  g_pP + (size_t)t * NN);
    chol_ldl(M3, dv, rdv);
    triinv_scaled(X, M3, rdv, dv);
    gemm64<0, false, ROW, ROW>(Pi, X, X, nullptr);                      // pPinv
    gemm64<0, false, 64,  ROW>(g_C + (size_t)(t - 1) * NN, APs, Pi,
                               nullptr, nullptr,
                               g_CT + (size_t)(t - 1) * NN);            // C = AP^T pPinv
}

// ---------------------------------------------------------------------------
// Kernel 2: forward means + log-likelihood (256 threads); runs CONCURRENTLY
// with kernel 1, self-paced via g_ready.  A/HA (and, for t>=NC, the steady
// Sinv/K) live in SMEM.  2 barriers per step.  logdet summed post-loop
// via __ldcg (stale-L1 line-sharing hazard).
// ---------------------------------------------------------------------------
__global__ void __launch_bounds__(256)
k_means_forward(const float* __restrict__ obs, const float* __restrict__ Ag,
                const float* __restrict__ bg, const float* __restrict__ Hg,
                const float* __restrict__ cg, const float* __restrict__ pm0,
                float* __restrict__ out_ll)
{
    extern __shared__ float smf[];
    float* sAH = smf;               // rows 0-63: A      ; rows 64-127: HA
    float* sSK = smf + 128 * ROW;   // rows 0-63: Sinv_ss; rows 64-127: K_ss
    __shared__ float x[64], o1[64], rres[64], sbh[128], wsum[4];
    const int tid = threadIdx.x;
    const int row = tid >> 1, h = tid & 1;
    const int lane = tid & 31, wid = tid >> 5;
    double ll = 0.0;
    const float llc = -58.81206612509907f;   // -0.5 * 64 * log(2*pi)

    // wait for producer step 1 (g_HA / g_bh / t=0 matrices ready), then stage
    if (tid == 0) while (atomicAdd(&g_ready, 0) < 1) __nanosleep(200);
    __syncthreads();
    for (int idx = tid; idx < 2 * NN; idx += 256) {
        const int r = idx >> 6, c = idx & 63;
        sAH[r * ROW + c] = (r < 64) ? Ag[idx] : __ldcg(&g_HA[(size_t)(r - 64) * 64 + c]);
    }
    if (tid < 64) sbh[tid] = bg[tid];
    else if (tid < 128) sbh[tid] = __ldcg(&g_bh[tid - 64]);
    if (tid < 64) x[tid] = pm0[tid];
    __syncthreads();

    for (int t = 0; t < TT; t++) {
        const int tc = (t < NC) ? t : (NC - 1);
        if (t > 0 && t < NC) {                  // pace behind the producer
            if (tid == 0)
                while (atomicAdd(&g_ready, 0) < t + 1) __nanosleep(200);
            __syncthreads();
        }
        if (t == NC) {                          // one-time stage of steady Sinv/K
            for (int idx = tid; idx < 2 * NN; idx += 256) {
                const int r = idx >> 6, c = idx & 63;
                sSK[r * ROW + c] = (r < 64)
                    ? __ldcg(&g_Sinv[(size_t)(NC - 1) * NN + r * 64 + c])
                    : __ldcg(&g_K[(size_t)(NC - 1) * NN + (size_t)(r - 64) * 64 + c]);
            }
            __syncthreads();
        }

        // ---- phase 1: rows<64 -> pm ; rows>=64 -> yhat, rres -------------
        if (t == 0) {
            if (row < 64) {
                if (h == 0) { o1[row] = x[row]; g_pm[row] = x[row]; }
            } else {
                const float ob = __ldg(&obs[row - 64]);
                const float4* M4 = (const float4*)(Hg + (size_t)(row - 64) * 64 + h * 32);
                float s = 0.0f;
                #pragma unroll
                for (int q = 0; q < 8; q++) {
                    const float4 v = M4[q];
                    const int k = h * 32 + q * 4;
                    s += v.x * x[k] + v.y * x[k + 1] + v.z * x[k + 2] + v.w * x[k + 3];
                }
                s += __shfl_down_sync(0xffffffffu, s, 1, 2);
                if (h == 0) rres[row - 64] = ob - (s + __ldg(&cg[row - 64]));
            }
        } else {
            float ob = 0.0f;
            if (row >= 64 && h == 0) ob = __ldg(&obs[(size_t)t * 64 + (row - 64)]);
            const float4* M4 = (const float4*)(sAH + row * ROW + h * 32);
            float s = 0.0f;
            #pragma unroll
            for (int q = 0; q < 8; q++) {
                const float4 v = M4[q];
                const int k = h * 32 + q * 4;
                s += v.x * x[k] + v.y * x[k + 1] + v.z * x[k + 2] + v.w * x[k + 3];
            }
            s += __shfl_down_sync(0xffffffffu, s, 1, 2);
            if (h == 0) {
                const float sv = s + sbh[row];
                if (row < 64) { o1[row] = sv; g_pm[(size_t)t * 64 + row] = sv; }
                else          rres[row - 64] = ob - sv;
            }
        }
        __syncthreads();

        // ---- phase 2: rows<64 -> r^T Sinv r part ; rows>=64 -> fm --------
        float s2 = 0.0f;
        if (t < NC) {
            const float* Mr = (row < 64)
                ? (g_Sinv + (size_t)tc * NN + row * 64)
                : (g_K + (size_t)tc * NN + (size_t)(row - 64) * 64);
            const float4* M4 = (const float4*)(Mr + h * 32);
            #pragma unroll
            for (int q = 0; q < 8; q++) {
                const float4 v = M4[q];
                const int k = h * 32 + q * 4;
                s2 += v.x * rres[k] + v.y * rres[k + 1] + v.z * rres[k + 2] + v.w * rres[k + 3];
            }
        } else {
            const float4* M4 = (const float4*)(sSK + row * ROW + h * 32);
            #pragma unroll
            for (int q = 0; q < 8; q++) {
                const float4 v = M4[q];
                const int k = h * 32 + q * 4;
                s2 += v.x * rres[k] + v.y * rres[k + 1] + v.z * rres[k + 2] + v.w * rres[k + 3];
            }
        }
        s2 += __shfl_down_sync(0xffffffffu, s2, 1, 2);

        if (row < 64) {                          // warps 0-3: quadratic form
            float contrib = (h == 0) ? rres[row] * s2 : 0.0f;
            #pragma unroll
            for (int o = 16; o > 0; o >>= 1)
                contrib += __shfl_down_sync(0xffffffffu, contrib, o);
            if (lane == 0) wsum[wid] = contrib;
        } else if (h == 0) {                     // warps 4-7: fm = pm + K r
            const float f = o1[row - 64] + s2;
            x[row - 64] = f;
            g_fm[(size_t)t * 64 + (row - 64)] = f;
        }
        __syncthreads();

        if (tid == 0)
            ll += (double)(llc - 0.5f * (wsum[0] + wsum[1] + wsum[2] + wsum[3]));
        // safe: tid0's wsum read precedes its phase-1 barrier of t+1, which
        // precedes any t+1 wsum write.
    }

    // logdet contribution: producer fully done (loop paced to t=NC-1).
    if (tid == 0) {
        double lds = 0.0;
        for (int t = 0; t < NC - 1; t++) lds += (double)__ldcg(&g_logdet[t]);
        lds += (double)(TT - (NC - 1)) * (double)__ldcg(&g_logdet[NC - 1]);
        *out_ll = (float)(ll - lds);
    }
}

// ---------------------------------------------------------------------------
// Kernel 3: backward smoothed covariances.  grid=2:
//   CTA 0: tail region [TB, T-2] (steady coefficients), sequential NTAIL.
//   CTA 1: fixed-point doubling to steady sP (log steps), writes g_sPbss,
//          then head region [0, NC-1] with exact per-t coefficients.
// ---------------------------------------------------------------------------
__global__ void __launch_bounds__(NT)
k_cov_backward(float* __restrict__ out_cov)
{
    extern __shared__ float sm[];
    float* sP  = sm + 0 * MAT;   // carried sP  (CTA1: doubling B)
    float* Cst = sm + 1 * MAT;   // C^T         (CTA1: doubling M^T)
    float* Dm  = sm + 2 * MAT;   // temp
    float* Em  = sm + 3 * MAT;   // temp
    float* pPs = sm + 4 * MAT;   // steady pP
    float* Tm  = sm + 5 * MAT;   // doubling temp
    const int tid = threadIdx.x;

    const float* fPs = g_fP + (size_t)(NC - 1) * NN;

    if (blockIdx.x == 0) {
        // ---- tail: t = T-1 then [TB, T-2], steady coefficients ----
        g2s(sP, fPs);
        s2g(out_cov + (size_t)(TT - 1) * NN, sP);
        g2s(Cst, g_CT + (size_t)(NC - 2) * NN);
        g2s(pPs, g_pP + (size_t)(NC - 1) * NN);
        for (int t = TT - 2; t >= TB; t--) {
            for (int idx = tid; idx < MAT / 4; idx += NT)
                ((float4*)Dm)[idx] = make_float4(
                    ((const float4*)sP)[idx].x - ((const float4*)pPs)[idx].x,
                    ((const float4*)sP)[idx].y - ((const float4*)pPs)[idx].y,
                    ((const float4*)sP)[idx].z - ((const float4*)pPs)[idx].z,
                    ((const float4*)sP)[idx].w - ((const float4*)pPs)[idx].w);
            gemm64<0, false, ROW, ROW>(Em, Cst, Dm, nullptr);  // E = C (sP - pP)
            gemm64<1, true,  ROW, 64 >(sP, Em, Cst, fPs);      // sP = fP + E C^T
            s2g(out_cov + (size_t)t * NN, sP);
        }
    } else {
        // ---- doubling: fixed point of  sP -> C sP C^T + G,
        //      G = fP_ss - C pP_ss C^T.  M stored transposed in Cst. ----
        g2s(Cst, g_CT + (size_t)(NC - 2) * NN);                 // M^T = C^T
        g2s(pPs, g_pP + (size_t)(NC - 1) * NN);
        gemm64<0, false, ROW, ROW>(Tm, Cst, pPs, nullptr);      // T = C pP
        gemm64<2, true,  ROW, 64 >(sP, Tm, Cst, fPs);           // B = fP - T C^T
        float* Mt = Cst;
        float* Sq = Em;
        for (int it = 0; it < 8; it++) {
            gemm64<0, false, ROW, ROW>(Tm, Mt, sP, nullptr);    // T = M B
            gemm64<1, true,  ROW, ROW>(sP, Tm, Mt, sP);         // B += T M^T
            gemm64<0, true,  ROW, ROW>(Sq, Mt, Mt, nullptr);    // (M^2)^T
            float* tmp = Mt; Mt = Sq; Sq = tmp;                 // M <- M^2
        }
        s2g(g_sPbss, sP);                                       // steady value

        // ---- head region [0, NC-1], exact per-t coefficients ----
        for (int t = NC - 1; t >= 0; t--) {
            const int tcC = (t < NC - 1) ? t : (NC - 2);
            const int tcn = (t + 1 < NC) ? (t + 1) : (NC - 1);
            g2s(Sq, g_CT + (size_t)tcC * NN);                   // C^T for this t
            const float4* gpP = (const float4*)(g_pP + (size_t)tcn * NN);
            for (int idx = tid; idx < 1024; idx += NT) {
                const int r = idx >> 4, c4 = idx & 15;
                const float4 a = ((const float4*)sP)[r * (ROW / 4) + c4];
                const float4 p = gpP[r * 16 + c4];
                ((float4*)Dm)[r * (ROW / 4) + c4] =
                    make_float4(a.x - p.x, a.y - p.y, a.z - p.z, a.w - p.w);
            }
            gemm64<0, false, ROW, ROW>(Tm, Sq, Dm, nullptr);    // T = C (sP - pP)
            gemm64<1, true,  ROW, 64 >(sP, Tm, Sq, g_fP + (size_t)t * NN);
            s2g(out_cov + (size_t)t * NN, sP);
        }
    }
}

// Kernel 4: fill the converged middle region [NC, TB) with the steady value.
__global__ void k_fill(float* __restrict__ out_cov)
{
    const size_t start = (size_t)NC * NN;
    const size_t end   = (size_t)TB * NN;
    const size_t stride = (size_t)gridDim.x * blockDim.x;
    for (size_t i = start + (size_t)blockIdx.x * blockDim.x + threadIdx.x;
         i < end; i += stride)
        out_cov[i] = g_sPbss[i & (NN - 1)];
}

// ---------------------------------------------------------------------------
// Kernel 5: backward smoothed means (all T steps, 256 threads).
// Steady C cached in SMEM (used for t >= NC-1, i.e. ~3999 steps);
// next step's pm/fm software-prefetched into registers.
// ---------------------------------------------------------------------------
__global__ void __launch_bounds__(256)
k_means_backward(float* __restrict__ out_sm)
{
    extern __shared__ float smb[];   // steady C, padded ROW
    __shared__ float smv[64], d[64], fmsh[64];
    const int tid = threadIdx.x;
    const int row = tid >> 2, q = tid & 3;

    for (int idx = tid; idx < NN; idx += 256) {
        const int r = idx >> 6, c = idx & 63;
        smb[r * ROW + c] = __ldg(&g_C[(size_t)(NC - 2) * NN + idx]);
    }
    float pmn = 0.0f, fmt = 0.0f;
    if (tid < 64) {
        const float v = __ldg(&g_fm[(size_t)(TT - 1) * 64 + tid]);
        smv[tid] = v;
        out_sm[(size_t)(TT - 1) * 64 + tid] = v;
        pmn = __ldg(&g_pm[(size_t)(TT - 1) * 64 + tid]);
        fmt = __ldg(&g_fm[(size_t)(TT - 2) * 64 + tid]);
    }
    __syncthreads();

    for (int t = TT - 2; t >= 0; t--) {
        if (tid < 64) { d[tid] = smv[tid] - pmn; fmsh[tid] = fmt; }
        if (t > 0 && tid < 64) {                 // prefetch for next iteration
            pmn = __ldg(&g_pm[(size_t)t * 64 + tid]);
            fmt = __ldg(&g_fm[(size_t)(t - 1) * 64 + tid]);
        }
        __syncthreads();

        float s = 0.0f;
        if (t >= NC - 1) {
            const float4* M4 = (const float4*)(smb + row * ROW + q * 16);
            #pragma unroll
            for (int p = 0; p < 4; p++) {
                const float4 v = M4[p];
                const int k = q * 16 + p * 4;
                s += v.x * d[k] + v.y * d[k + 1] + v.z * d[k + 2] + v.w * d[k + 3];
            }
        } else {
            const float4* M4 = (const float4*)(g_C + (size_t)t * NN + row * 64 + q * 16);
            #pragma unroll
            for (int p = 0; p < 4; p++) {
                const float4 v = M4[p];
                const int k = q * 16 + p * 4;
                s += v.x * d[k] + v.y * d[k + 1] + v.z * d[k + 2] + v.w * d[k + 3];
            }
        }
        s += __shfl_down_sync(0xffffffffu, s, 2, 4);
        s += __shfl_down_sync(0xffffffffu, s, 1, 4);
        if (q == 0) {
            const float nv = fmsh[row] + s;
            smv[row] = nv;
            out_sm[(size_t)t * 64 + row] = nv;
        }
        __syncthreads();
    }
}

// ---------------------------------------------------------------------------
extern "C" void kernel_launch(void* const* d_in, const int* in_sizes, int n_in,
                              void* d_out, int out_size)
{
    (void)in_sizes; (void)n_in; (void)out_size;
    const float* obs = (const float*)d_in[0];
    const float* A   = (const float*)d_in[1];
    const float* b   = (const float*)d_in[2];
    const float* Q   = (const float*)d_in[3];
    const float* H   = (const float*)d_in[4];
    const float* c   = (const float*)d_in[5];
    const float* R   = (const float*)d_in[6];
    const float* pm0 = (const float*)d_in[7];
    const float* pP0 = (const float*)d_in[8];

    float* out     = (float*)d_out;
    float* out_sm  = out;                                        // [T,64]
    float* out_cov = out + (size_t)TT * 64;                      // [T,64,64]
    float* out_ll  = out + (size_t)TT * 64 + (size_t)TT * NN;    // scalar

    static cudaStream_t s2 = nullptr;
    static cudaEvent_t ev0, evG, evE;
    if (!s2) {
        cudaStreamCreateWithFlags(&s2, cudaStreamNonBlocking);
        cudaEventCreateWithFlags(&ev0, cudaEventDisableTiming);
        cudaEventCreateWithFlags(&evG, cudaEventDisableTiming);
        cudaEventCreateWithFlags(&evE, cudaEventDisableTiming);
        cudaFuncSetAttribute((const void*)k_cov_forward,
                             cudaFuncAttributeMaxDynamicSharedMemorySize,
                             11 * MAT * (int)sizeof(float));
        cudaFuncSetAttribute((const void*)k_gains,
                             cudaFuncAttributeMaxDynamicSharedMemorySize,
                             4 * MAT * (int)sizeof(float));
        cudaFuncSetAttribute((const void*)k_cov_backward,
                             cudaFuncAttributeMaxDynamicSharedMemorySize,
                             6 * MAT * (int)sizeof(float));
        cudaFuncSetAttribute((const void*)k_means_forward,
                             cudaFuncAttributeMaxDynamicSharedMemorySize,
                             2 * 128 * ROW * (int)sizeof(float));
    }

    // Fork: means_forward runs concurrently with cov_forward (flag-paced).
    cudaEventRecord(ev0, 0);
    cudaStreamWaitEvent(s2, ev0, 0);
    k_means_forward<<<1, 256, 2 * 128 * ROW * sizeof(float), s2>>>(
        obs, A, b, H, c, pm0, out_ll);

    k_cov_forward<<<1, NT, 11 * MAT * sizeof(float)>>>(A, b, Q, H, c, R, pP0);
    k_gains<<<NC - 1, NT, 4 * MAT * sizeof(float)>>>();
    cudaEventRecord(evG, 0);
    k_cov_backward<<<2, NT, 6 * MAT * sizeof(float)>>>(out_cov);
    k_fill<<<1024, 256>>>(out_cov);

    cudaStreamWaitEvent(s2, evG, 0);          // means_backward needs g_C
    k_means_backward<<<1, 256, MAT * sizeof(float), s2>>>(out_sm);

    cudaEventRecord(evE, s2);                 // join
    cudaStreamWaitEvent(0, evE, 0);
}